// round 1
// baseline (speedup 1.0000x reference)
#include <cuda_runtime.h>

// Problem constants (from reference)
#define B_  128
#define T_  32
#define D_  512
// N = B*T*D = 2,097,152 floats; N4 = 524,288 float4
#define N4_ (B_ * T_ * D_ / 4)
#define D4_ (D_ / 4)   // 128

// Persistent accumulators. Invariant: zero at kernel entry.
// (Initialized zero at module load; last block resets them via atomicExch.)
__device__ float    g_acc[2] = {0.f, 0.f};
__device__ unsigned g_count  = 0u;

// out layout (flattened reference return tuple):
//   out[0] = sl_rhat
//   out[1] = sl_rbar
//   out[2] = TEMP_WEIGHT * temp_loss = 0
//   out[3] = r2_losses = 0
//   out[4 .. 4+B*R)          = r0 (zeros)
//   out[4+B*R .. out_size)   = r2 (zeros)
__global__ void tidhy_reduce_kernel(const float4* __restrict__ X4,
                                    const float4* __restrict__ bsd4,
                                    float* __restrict__ out,
                                    int out_size)
{
    const int tid     = blockIdx.x * blockDim.x + threadIdx.x;
    const int nthread = gridDim.x * blockDim.x;

    // ---- zero-fill out[2 .. out_size) (r0, r2, temp_loss, r2_losses) ----
    for (int i = 2 + tid; i < out_size; i += nthread)
        out[i] = 0.0f;

    // ---- fused reduction: sum over all (b,t,d) of (X - b_sd)^2,
    //      and separately the t==0 slice ----
    float s_all = 0.0f;
    float s_t0  = 0.0f;
    for (int i = tid; i < N4_; i += nthread) {
        float4 x = X4[i];
        float4 b = bsd4[i & (D4_ - 1)];          // d-index = i % 128 (float4 units)
        float dx = x.x - b.x;
        float dy = x.y - b.y;
        float dz = x.z - b.z;
        float dw = x.w - b.w;
        float v  = dx * dx + dy * dy + dz * dz + dw * dw;
        s_all += v;
        // t = (i / D4) % T ; contribute to t0-sum only when t == 0
        if (((i / D4_) & (T_ - 1)) == 0)
            s_t0 += v;
    }

    // ---- intra-block reduction ----
    #pragma unroll
    for (int o = 16; o > 0; o >>= 1) {
        s_all += __shfl_xor_sync(0xffffffffu, s_all, o);
        s_t0  += __shfl_xor_sync(0xffffffffu, s_t0,  o);
    }
    __shared__ float sh_a[32], sh_t[32];
    const int lane = threadIdx.x & 31;
    const int wid  = threadIdx.x >> 5;
    if (lane == 0) { sh_a[wid] = s_all; sh_t[wid] = s_t0; }
    __syncthreads();

    if (wid == 0) {
        const int nw = blockDim.x >> 5;
        float a = (lane < nw) ? sh_a[lane] : 0.0f;
        float t = (lane < nw) ? sh_t[lane] : 0.0f;
        #pragma unroll
        for (int o = 16; o > 0; o >>= 1) {
            a += __shfl_xor_sync(0xffffffffu, a, o);
            t += __shfl_xor_sync(0xffffffffu, t, o);
        }
        if (lane == 0) {
            // g_acc[0] += sum_all ; g_acc[1] += sum_{t>=1}
            atomicAdd(&g_acc[0], a);
            atomicAdd(&g_acc[1], a - t);
            __threadfence();
            // last block finalizes; atomicInc wraps counter back to 0
            unsigned old = atomicInc(&g_count, gridDim.x - 1);
            if (old == gridDim.x - 1) {
                // atomicExch = coherent L2 read + reset (keeps zero-invariant
                // for the next graph replay)
                float tot_all = atomicExch(&g_acc[0], 0.0f);
                float tot_r   = atomicExch(&g_acc[1], 0.0f);
                out[0] = tot_all * (1.0f / (float)B_);  // sl_rhat
                out[1] = tot_r   * (1.0f / (float)B_);  // sl_rbar
            }
        }
    }
}

extern "C" void kernel_launch(void* const* d_in, const int* in_sizes, int n_in,
                              void* d_out, int out_size)
{
    // metadata order: X, rng, W_sd, b_sd, W_h1, b_h1, ln_scale, ln_bias,
    //                 W_h2, b_h2, W_h3, b_h3, temporal
    const float4* X4   = (const float4*)d_in[0];
    const float4* bsd4 = (const float4*)d_in[3];
    float* out = (float*)d_out;

    // 296 blocks (2 waves of CTAs won't happen: 296 ≈ 2 per SM) x 256 threads:
    // ~7 float4 loads per thread -> good MLP, memory-bound saturation.
    tidhy_reduce_kernel<<<296, 256>>>(X4, bsd4, out, out_size);
}